// round 7
// baseline (speedup 1.0000x reference)
#include <cuda_runtime.h>
#include <cuda_bf16.h>
#include <math.h>

// Problem constants
#define BQ 2
#define SQ 2048
#define DM 1024
#define NH 16
#define DK 64
#define MROWS (BQ*SQ)   // 4096

// ---------------- scratch (allocation-free rule: __device__ globals) ----------------
__device__ float g_q[MROWS * DM];
__device__ float g_k[MROWS * DM];
__device__ float g_v[MROWS * DM];
__device__ float g_ctx[MROWS * DM];
__device__ float g_rq[MROWS * DM];
__device__ float g_rk[MROWS * DM];
__device__ float g_rv[MROWS * DM];
__device__ float g_wq[DM * DM];
__device__ float g_wk[DM * DM];
__device__ float g_wv[DM * DM];
__device__ float g_wo[DM * DM];

// =====================================================================
// helpers
// =====================================================================
__device__ __forceinline__ float f2tf32(float f) {
    unsigned r;
    asm("cvt.rna.tf32.f32 %0, %1;" : "=r"(r) : "f"(f));
    return __uint_as_float(r);
}

__device__ __forceinline__ void mma_tf32(float* c, const unsigned* a, unsigned b0, unsigned b1) {
    asm volatile(
        "mma.sync.aligned.m16n8k8.row.col.f32.tf32.tf32.f32 "
        "{%0,%1,%2,%3}, {%4,%5,%6,%7}, {%8,%9}, {%0,%1,%2,%3};"
        : "+f"(c[0]), "+f"(c[1]), "+f"(c[2]), "+f"(c[3])
        : "r"(a[0]), "r"(a[1]), "r"(a[2]), "r"(a[3]), "r"(b0), "r"(b1));
}

__device__ __forceinline__ float ex2(float x) {
    float y;
    asm("ex2.approx.f32 %0, %1;" : "=f"(y) : "f"(x));
    return y;
}

__device__ __forceinline__ void cpa16(float* s, const float* g) {
    unsigned a = (unsigned)__cvta_generic_to_shared(s);
    asm volatile("cp.async.ca.shared.global [%0], [%1], 16;" :: "r"(a), "l"(g));
}
#define CP_COMMIT() asm volatile("cp.async.commit_group;")
#define CP_WAIT(n)  asm volatile("cp.async.wait_group %0;" :: "n"(n))

// k-dim permutation within each 8-group: storage position of original col c
// layout per group: [c0, c4, c1, c5, c2, c6, c3, c7]
__device__ __forceinline__ int loc8(int c) { return (c < 4) ? 2 * c : 2 * (c - 4) + 1; }

// =====================================================================
// prepass: round to tf32 + permute k-dim 8-groups. 8 floats per thread.
// =====================================================================
__global__ void __launch_bounds__(256) round_perm(
    const float4* __restrict__ in, float4* __restrict__ out, int n8)
{
    int i = blockIdx.x * 256 + threadIdx.x;
    if (i < n8) {
        float4 x0 = in[i * 2];
        float4 x1 = in[i * 2 + 1];
        out[i * 2]     = make_float4(f2tf32(x0.x), f2tf32(x1.x), f2tf32(x0.y), f2tf32(x1.y));
        out[i * 2 + 1] = make_float4(f2tf32(x0.z), f2tf32(x1.z), f2tf32(x0.w), f2tf32(x1.w));
    }
}

__global__ void __launch_bounds__(256) round_perm_w4(
    const float4* __restrict__ w0, const float4* __restrict__ w1,
    const float4* __restrict__ w2, const float4* __restrict__ w3,
    float4* __restrict__ o0, float4* __restrict__ o1,
    float4* __restrict__ o2, float4* __restrict__ o3, int n8)
{
    int z = blockIdx.y;
    const float4* in = (z == 0) ? w0 : (z == 1) ? w1 : (z == 2) ? w2 : w3;
    float4* out      = (z == 0) ? o0 : (z == 1) ? o1 : (z == 2) ? o2 : o3;
    int i = blockIdx.x * 256 + threadIdx.x;
    if (i < n8) {
        float4 x0 = in[i * 2];
        float4 x1 = in[i * 2 + 1];
        out[i * 2]     = make_float4(f2tf32(x0.x), f2tf32(x1.x), f2tf32(x0.y), f2tf32(x1.y));
        out[i * 2 + 1] = make_float4(f2tf32(x0.z), f2tf32(x1.z), f2tf32(x0.w), f2tf32(x1.w));
    }
}

// =====================================================================
// Pipelined tf32 GEMM (k-dim pre-permuted): C = A @ W^T + bias
// 128x128x32 tiles, 2-stage cp.async, LDS.64 fragment loads.
// mode=1: round output to tf32 and permute output 8-groups (QKV).
// mode=0: plain fp32 output (O projection).
// =====================================================================
#define SAP 40
#define GEMM_SMEM (2 * 2 * 128 * SAP * 4)   // 81920 B

__global__ void __launch_bounds__(256, 2) gemm3(
    const float* __restrict__ A0, const float* __restrict__ A1, const float* __restrict__ A2,
    const float* __restrict__ W0, const float* __restrict__ W1, const float* __restrict__ W2,
    const float* __restrict__ B0, const float* __restrict__ B1, const float* __restrict__ B2,
    float* __restrict__ C0, float* __restrict__ C1, float* __restrict__ C2,
    int mode)
{
    extern __shared__ float sm[];
    float* As = sm;                     // [2][128*SAP]
    float* Ws = sm + 2 * 128 * SAP;     // [2][128*SAP]

    int z = blockIdx.z;
    const float* A    = (z == 0) ? A0 : (z == 1) ? A1 : A2;
    const float* W    = (z == 0) ? W0 : (z == 1) ? W1 : W2;
    const float* bias = (z == 0) ? B0 : (z == 1) ? B1 : B2;
    float*       C    = (z == 0) ? C0 : (z == 1) ? C1 : C2;

    int tid = threadIdx.x;
    int m0 = blockIdx.y * 128;
    int n0 = blockIdx.x * 128;
    const float* Ab = A + (size_t)m0 * DM;
    const float* Wb = W + (size_t)n0 * DM;

    auto issue = [&](int kt, int st) {
        float* sA = As + st * 128 * SAP;
        float* sW = Ws + st * 128 * SAP;
        int k0 = kt * 32;
        #pragma unroll
        for (int i = 0; i < 4; i++) {
            int c = tid + i * 256;          // 0..1023
            int row = c >> 3;
            int col = (c & 7) << 2;
            cpa16(sA + row * SAP + col, Ab + (size_t)row * DM + k0 + col);
            cpa16(sW + row * SAP + col, Wb + (size_t)row * DM + k0 + col);
        }
        CP_COMMIT();
    };

    issue(0, 0);

    int w    = tid >> 5;
    int lane = tid & 31;
    int wm = (w >> 1) * 32;
    int wn = (w & 1) * 64;
    int g = lane >> 2;
    int t = lane & 3;

    float acc[2][8][4] = {};

    const int NT = DM / 32;   // 32
    for (int kt = 0; kt < NT; kt++) {
        int buf = kt & 1;
        if (kt + 1 < NT) { issue(kt + 1, buf ^ 1); CP_WAIT(1); }
        else             { CP_WAIT(0); }
        __syncthreads();

        const float* ab = As + buf * 128 * SAP;
        const float* wb = Ws + buf * 128 * SAP;
        #pragma unroll
        for (int ks = 0; ks < 4; ks++) {
            unsigned af[2][4];
            #pragma unroll
            for (int mt = 0; mt < 2; mt++) {
                const float* bp = ab + (wm + mt * 16 + g) * SAP + ks * 8 + 2 * t;
                float2 lo = *(const float2*)bp;
                float2 hi = *(const float2*)(bp + 8 * SAP);
                af[mt][0] = __float_as_uint(lo.x);
                af[mt][1] = __float_as_uint(hi.x);
                af[mt][2] = __float_as_uint(lo.y);
                af[mt][3] = __float_as_uint(hi.y);
            }
            #pragma unroll
            for (int nt = 0; nt < 8; nt++) {
                float2 bb = *(const float2*)(wb + (wn + nt * 8 + g) * SAP + ks * 8 + 2 * t);
                unsigned b0 = __float_as_uint(bb.x);
                unsigned b1 = __float_as_uint(bb.y);
                mma_tf32(acc[0][nt], af[0], b0, b1);
                mma_tf32(acc[1][nt], af[1], b0, b1);
            }
        }
        __syncthreads();
    }

    int l0i = loc8(2 * t);
    int l1i = loc8(2 * t + 1);
    #pragma unroll
    for (int mt = 0; mt < 2; mt++) {
        #pragma unroll
        for (int nt = 0; nt < 8; nt++) {
            int m = m0 + wm + mt * 16 + g;
            int ng = n0 + wn + nt * 8;
            float bn0 = bias[ng + 2 * t];
            float bn1 = bias[ng + 2 * t + 1];
            float r0 = acc[mt][nt][0] + bn0;
            float r1 = acc[mt][nt][1] + bn1;
            float r2 = acc[mt][nt][2] + bn0;
            float r3 = acc[mt][nt][3] + bn1;
            if (mode) {
                // round + permute output 8-groups (feeds next contraction)
                C[(size_t)m * DM + ng + l0i]       = f2tf32(r0);
                C[(size_t)m * DM + ng + l1i]       = f2tf32(r1);
                C[(size_t)(m + 8) * DM + ng + l0i] = f2tf32(r2);
                C[(size_t)(m + 8) * DM + ng + l1i] = f2tf32(r3);
            } else {
                *(float2*)&C[(size_t)m * DM + ng + 2 * t]       = make_float2(r0, r1);
                *(float2*)&C[(size_t)(m + 8) * DM + ng + 2 * t] = make_float2(r2, r3);
            }
        }
    }
}

// =====================================================================
// Tensor-core flash attention, 2-stage cp.async KV pipeline,
// quad-shuffle P transpose, LDS.64 fragment loads (dk pre-permuted in Q,K).
// V dk-columns pre-permuted too -> ctx comes out permuted for the O-gemm.
// CTA: 128 q-rows x one (b,h); 8 warps x 16 q-rows. KV tiles of 64.
// =====================================================================
#define KQP 72
#define FA_SMEM ((128 * KQP + 2 * 64 * KQP + 2 * 64 * KQP) * 4)   // 110592 B

__global__ void __launch_bounds__(256, 2) flash_mma(
    const float* __restrict__ Qg,
    const float* __restrict__ Kg,
    const float* __restrict__ Vg,
    float* __restrict__ Ctx)
{
    extern __shared__ float sm[];
    float* Qs = sm;                        // [128][KQP]
    float* Kd = Qs + 128 * KQP;            // [2][64][KQP]
    float* Vd = Kd + 2 * 64 * KQP;         // [2][64][KQP]

    int tid  = threadIdx.x;
    int w    = tid >> 5;
    int lane = tid & 31;
    int g = lane >> 2;
    int t = lane & 3;
    int wr = w * 16;

    int q0 = blockIdx.x * 128;
    int h  = blockIdx.y;
    int b  = blockIdx.z;

    const size_t base = (size_t)b * SQ * DM + (size_t)h * DK;
    const float* Qb = Qg + base;
    const float* Kb = Kg + base;
    const float* Vb = Vg + base;

    auto issue = [&](int it, int buf) {
        const float* ksrc = Kb + (size_t)(it * 64) * DM;
        const float* vsrc = Vb + (size_t)(it * 64) * DM;
        float* kdst = Kd + buf * 64 * KQP;
        float* vdst = Vd + buf * 64 * KQP;
        #pragma unroll
        for (int i = 0; i < 4; i++) {
            int c = tid + i * 256;         // 0..1023
            int row = c >> 4;
            int col = (c & 15) << 2;
            cpa16(kdst + row * KQP + col, ksrc + (size_t)row * DM + col);
            cpa16(vdst + row * KQP + col, vsrc + (size_t)row * DM + col);
        }
        CP_COMMIT();
    };

    issue(0, 0);

    // Q tile (pre-rounded + pre-permuted): plain copy
    for (int i = tid; i < 128 * 16; i += 256) {
        int r  = i >> 4;
        int c4 = (i & 15) << 2;
        *(float4*)(Qs + r * KQP + c4) = *(const float4*)(Qb + (size_t)(q0 + r) * DM + c4);
    }

    float m0 = -1e30f, m1 = -1e30f;
    float l0 = 0.0f,   l1 = 0.0f;
    float o[8][4] = {};
    const float CS = 0.125f * 1.44269504f;   // scale * log2(e)

    const int NT = SQ / 64;   // 32
    int src0 = (lane & ~3) | (t >> 1);
    bool odd = t & 1;

    for (int it = 0; it < NT; it++) {
        int buf = it & 1;
        if (it + 1 < NT) { issue(it + 1, buf ^ 1); CP_WAIT(1); }
        else             { CP_WAIT(0); }
        __syncthreads();

        const float* Ks = Kd + buf * 64 * KQP;
        const float* Vs = Vd + buf * 64 * KQP;

        // ---- S = Q @ K^T  (LDS.64 fragment loads on permuted layout) ----
        float sc[8][4] = {};
        #pragma unroll
        for (int ks = 0; ks < 8; ks++) {
            const float* ab = Qs + (wr + g) * KQP + ks * 8 + 2 * t;
            float2 alo = *(const float2*)ab;
            float2 ahi = *(const float2*)(ab + 8 * KQP);
            unsigned a[4];
            a[0] = __float_as_uint(alo.x);
            a[1] = __float_as_uint(ahi.x);
            a[2] = __float_as_uint(alo.y);
            a[3] = __float_as_uint(ahi.y);
            #pragma unroll
            for (int nb = 0; nb < 8; nb++) {
                float2 bb = *(const float2*)(Ks + (nb * 8 + g) * KQP + ks * 8 + 2 * t);
                mma_tf32(sc[nb], a, __float_as_uint(bb.x), __float_as_uint(bb.y));
            }
        }

        // ---- online softmax (log2 domain) ----
        float mx0 = m0, mx1 = m1;
        #pragma unroll
        for (int nb = 0; nb < 8; nb++) {
            sc[nb][0] *= CS; sc[nb][1] *= CS; sc[nb][2] *= CS; sc[nb][3] *= CS;
            mx0 = fmaxf(mx0, fmaxf(sc[nb][0], sc[nb][1]));
            mx1 = fmaxf(mx1, fmaxf(sc[nb][2], sc[nb][3]));
        }
        mx0 = fmaxf(mx0, __shfl_xor_sync(0xffffffffu, mx0, 1));
        mx0 = fmaxf(mx0, __shfl_xor_sync(0xffffffffu, mx0, 2));
        mx1 = fmaxf(mx1, __shfl_xor_sync(0xffffffffu, mx1, 1));
        mx1 = fmaxf(mx1, __shfl_xor_sync(0xffffffffu, mx1, 2));

        float a0 = 1.0f, a1 = 1.0f;
        if (__any_sync(0xffffffffu, (mx0 > m0) | (mx1 > m1))) {
            a0 = ex2(m0 - mx0);
            a1 = ex2(m1 - mx1);
            #pragma unroll
            for (int nb = 0; nb < 8; nb++) {
                o[nb][0] *= a0; o[nb][1] *= a0;
                o[nb][2] *= a1; o[nb][3] *= a1;
            }
        }
        m0 = mx0; m1 = mx1;

        float s0 = 0.0f, s1 = 0.0f;
        #pragma unroll
        for (int nb = 0; nb < 8; nb++) {
            float e00 = ex2(sc[nb][0] - mx0);
            float e01 = ex2(sc[nb][1] - mx0);
            float e10 = ex2(sc[nb][2] - mx1);
            float e11 = ex2(sc[nb][3] - mx1);
            s0 += e00 + e01;
            s1 += e10 + e11;
            sc[nb][0] = f2tf32(e00);
            sc[nb][1] = f2tf32(e01);
            sc[nb][2] = f2tf32(e10);
            sc[nb][3] = f2tf32(e11);
        }
        s0 += __shfl_xor_sync(0xffffffffu, s0, 1);
        s0 += __shfl_xor_sync(0xffffffffu, s0, 2);
        s1 += __shfl_xor_sync(0xffffffffu, s1, 1);
        s1 += __shfl_xor_sync(0xffffffffu, s1, 2);
        l0 = l0 * a0 + s0;
        l1 = l1 * a1 + s1;

        // ---- O += P @ V : quad-shuffle transpose of P ----
        #pragma unroll
        for (int ks = 0; ks < 8; ks++) {
            float v00 = __shfl_sync(0xffffffffu, sc[ks][0], src0);
            float v01 = __shfl_sync(0xffffffffu, sc[ks][1], src0);
            float v10 = __shfl_sync(0xffffffffu, sc[ks][2], src0);
            float v11 = __shfl_sync(0xffffffffu, sc[ks][3], src0);
            float w00 = __shfl_sync(0xffffffffu, sc[ks][0], src0 + 2);
            float w01 = __shfl_sync(0xffffffffu, sc[ks][1], src0 + 2);
            float w10 = __shfl_sync(0xffffffffu, sc[ks][2], src0 + 2);
            float w11 = __shfl_sync(0xffffffffu, sc[ks][3], src0 + 2);
            unsigned a[4];
            a[0] = __float_as_uint(odd ? v01 : v00);
            a[1] = __float_as_uint(odd ? v11 : v10);
            a[2] = __float_as_uint(odd ? w01 : w00);
            a[3] = __float_as_uint(odd ? w11 : w10);
            #pragma unroll
            for (int nb = 0; nb < 8; nb++) {
                const float* vb = Vs + (ks * 8 + t) * KQP + nb * 8 + g;
                mma_tf32(o[nb], a, __float_as_uint(vb[0]), __float_as_uint(vb[4 * KQP]));
            }
        }
        __syncthreads();
    }

    // ---- epilogue: normalize, round to tf32, write combined (already permuted
    //      dk-order since V columns were permuted) ----
    float il0 = 1.0f / l0;
    float il1 = 1.0f / l1;
    float* out0 = Ctx + (size_t)b * SQ * DM + (size_t)(q0 + wr + g) * DM + h * DK;
    float* out1 = out0 + 8 * DM;
    #pragma unroll
    for (int nb = 0; nb < 8; nb++) {
        *(float2*)(out0 + nb * 8 + 2 * t) =
            make_float2(f2tf32(o[nb][0] * il0), f2tf32(o[nb][1] * il0));
        *(float2*)(out1 + nb * 8 + 2 * t) =
            make_float2(f2tf32(o[nb][2] * il1), f2tf32(o[nb][3] * il1));
    }
}

// ---------------- launch ----------------
extern "C" void kernel_launch(void* const* d_in, const int* in_sizes, int n_in,
                              void* d_out, int out_size)
{
    const float* q   = (const float*)d_in[0];
    const float* k   = (const float*)d_in[1];
    const float* v   = (const float*)d_in[2];
    const float* W_q = (const float*)d_in[3];
    const float* b_q = (const float*)d_in[4];
    const float* W_k = (const float*)d_in[5];
    const float* b_k = (const float*)d_in[6];
    const float* W_v = (const float*)d_in[7];
    const float* b_v = (const float*)d_in[8];
    const float* W_o = (const float*)d_in[9];
    const float* b_o = (const float*)d_in[10];
    float* out = (float*)d_out;

    float *gq, *gk, *gv, *gctx, *grq, *grk, *grv, *gwq, *gwk, *gwv, *gwo;
    cudaGetSymbolAddress((void**)&gq,  g_q);
    cudaGetSymbolAddress((void**)&gk,  g_k);
    cudaGetSymbolAddress((void**)&gv,  g_v);
    cudaGetSymbolAddress((void**)&gctx, g_ctx);
    cudaGetSymbolAddress((void**)&grq, g_rq);
    cudaGetSymbolAddress((void**)&grk, g_rk);
    cudaGetSymbolAddress((void**)&grv, g_rv);
    cudaGetSymbolAddress((void**)&gwq, g_wq);
    cudaGetSymbolAddress((void**)&gwk, g_wk);
    cudaGetSymbolAddress((void**)&gwv, g_wv);
    cudaGetSymbolAddress((void**)&gwo, g_wo);

    // prepass: round to tf32 + permute k-dim 8-groups
    const int NA8 = MROWS * DM / 8;   // 524288
    const int NW8 = DM * DM / 8;      // 131072
    round_perm<<<NA8 / 256, 256>>>((const float4*)q, (float4*)grq, NA8);
    round_perm<<<NA8 / 256, 256>>>((const float4*)k, (float4*)grk, NA8);
    round_perm<<<NA8 / 256, 256>>>((const float4*)v, (float4*)grv, NA8);
    round_perm_w4<<<dim3(NW8 / 256, 4), 256>>>(
        (const float4*)W_q, (const float4*)W_k, (const float4*)W_v, (const float4*)W_o,
        (float4*)gwq, (float4*)gwk, (float4*)gwv, (float4*)gwo, NW8);

    cudaFuncSetAttribute(gemm3, cudaFuncAttributeMaxDynamicSharedMemorySize, GEMM_SMEM);
    cudaFuncSetAttribute(flash_mma, cudaFuncAttributeMaxDynamicSharedMemorySize, FA_SMEM);

    // fused Q/K/V projections (tf32-rounded + permuted outputs)
    gemm3<<<dim3(DM / 128, MROWS / 128, 3), 256, GEMM_SMEM>>>(
        grq, grk, grv, gwq, gwk, gwv, b_q, b_k, b_v, gq, gk, gv, 1);

    // flash attention (launch index 5 -> profiled by ncu -s 5 -c 1)
    flash_mma<<<dim3(SQ / 128, NH, BQ), 256, FA_SMEM>>>(gq, gk, gv, gctx);

    // output projection (fp32 output)
    gemm3<<<dim3(DM / 128, MROWS / 128, 1), 256, GEMM_SMEM>>>(
        gctx, gctx, gctx, gwo, gwo, gwo, b_o, b_o, b_o, out, out, out, 0);
}

// round 11
// speedup vs baseline: 1.4857x; 1.4857x over previous
#include <cuda_runtime.h>
#include <cuda_bf16.h>
#include <math.h>

// Problem constants
#define BQ 2
#define SQ 2048
#define DM 1024
#define NH 16
#define DK 64
#define MROWS (BQ*SQ)   // 4096

// ---------------- scratch (allocation-free rule: __device__ globals) ----------------
__device__ float g_q[MROWS * DM];
__device__ float g_k[MROWS * DM];
__device__ float g_v[MROWS * DM];
__device__ float g_ctx[MROWS * DM];
__device__ float g_rq[MROWS * DM];
__device__ float g_rk[MROWS * DM];
__device__ float g_rv[MROWS * DM];
__device__ float g_wq[DM * DM];
__device__ float g_wk[DM * DM];
__device__ float g_wv[DM * DM];
__device__ float g_wo[DM * DM];

// =====================================================================
// helpers
// =====================================================================
__device__ __forceinline__ float f2tf32(float f) {
    unsigned r;
    asm("cvt.rna.tf32.f32 %0, %1;" : "=r"(r) : "f"(f));
    return __uint_as_float(r);
}

__device__ __forceinline__ void mma_tf32(float* c, const unsigned* a, unsigned b0, unsigned b1) {
    asm volatile(
        "mma.sync.aligned.m16n8k8.row.col.f32.tf32.tf32.f32 "
        "{%0,%1,%2,%3}, {%4,%5,%6,%7}, {%8,%9}, {%0,%1,%2,%3};"
        : "+f"(c[0]), "+f"(c[1]), "+f"(c[2]), "+f"(c[3])
        : "r"(a[0]), "r"(a[1]), "r"(a[2]), "r"(a[3]), "r"(b0), "r"(b1));
}

__device__ __forceinline__ float ex2(float x) {
    float y;
    asm("ex2.approx.f32 %0, %1;" : "=f"(y) : "f"(x));
    return y;
}

__device__ __forceinline__ void cpa16(float* s, const float* g) {
    unsigned a = (unsigned)__cvta_generic_to_shared(s);
    asm volatile("cp.async.ca.shared.global [%0], [%1], 16;" :: "r"(a), "l"(g));
}
#define CP_COMMIT() asm volatile("cp.async.commit_group;")
#define CP_WAIT(n)  asm volatile("cp.async.wait_group %0;" :: "n"(n))

// =====================================================================
// prepass: round tensors to tf32 (RNA) into scratch.
// round_act: grid.y in {0,1,2} selects q/k/v.  round_w: grid.y selects W_q/k/v/o.
// =====================================================================
__global__ void __launch_bounds__(256) round_act(
    const float4* __restrict__ i0, const float4* __restrict__ i1, const float4* __restrict__ i2,
    float4* __restrict__ o0, float4* __restrict__ o1, float4* __restrict__ o2, int n4)
{
    int z = blockIdx.y;
    const float4* in = (z == 0) ? i0 : (z == 1) ? i1 : i2;
    float4* out      = (z == 0) ? o0 : (z == 1) ? o1 : o2;
    int i = blockIdx.x * 256 + threadIdx.x;
    if (i < n4) {
        float4 v = in[i];
        out[i] = make_float4(f2tf32(v.x), f2tf32(v.y), f2tf32(v.z), f2tf32(v.w));
    }
}

__global__ void __launch_bounds__(256) round_w(
    const float4* __restrict__ i0, const float4* __restrict__ i1,
    const float4* __restrict__ i2, const float4* __restrict__ i3,
    float4* __restrict__ o0, float4* __restrict__ o1,
    float4* __restrict__ o2, float4* __restrict__ o3, int n4)
{
    int z = blockIdx.y;
    const float4* in = (z == 0) ? i0 : (z == 1) ? i1 : (z == 2) ? i2 : i3;
    float4* out      = (z == 0) ? o0 : (z == 1) ? o1 : (z == 2) ? o2 : o3;
    int i = blockIdx.x * 256 + threadIdx.x;
    if (i < n4) {
        float4 v = in[i];
        out[i] = make_float4(f2tf32(v.x), f2tf32(v.y), f2tf32(v.z), f2tf32(v.w));
    }
}

// =====================================================================
// Pipelined tf32 GEMM: C[m,n] = sum_k A[m,k]*W[n,k] + bias[n]
// A,W pre-rounded tf32. 128x128x32 tiles, 3-stage cp.async.
// blockIdx.z selects among 3 (A,W,bias,C) sets (fused QKV).
// =====================================================================
#define SAP 36    // smem row stride (floats): banks 4g+t -> conflict-free
#define GSTG 3
#define GEMM_SMEM (2 * GSTG * 128 * SAP * 4)   // 110592 B

__global__ void __launch_bounds__(256, 2) gemm3(
    const float* __restrict__ A0, const float* __restrict__ A1, const float* __restrict__ A2,
    const float* __restrict__ W0, const float* __restrict__ W1, const float* __restrict__ W2,
    const float* __restrict__ B0, const float* __restrict__ B1, const float* __restrict__ B2,
    float* __restrict__ C0, float* __restrict__ C1, float* __restrict__ C2,
    int round_out)
{
    extern __shared__ float sm[];
    float* As = sm;                         // [3][128*SAP]
    float* Ws = sm + GSTG * 128 * SAP;      // [3][128*SAP]

    int z = blockIdx.z;
    const float* A    = (z == 0) ? A0 : (z == 1) ? A1 : A2;
    const float* W    = (z == 0) ? W0 : (z == 1) ? W1 : W2;
    const float* bias = (z == 0) ? B0 : (z == 1) ? B1 : B2;
    float*       C    = (z == 0) ? C0 : (z == 1) ? C1 : C2;

    int tid = threadIdx.x;
    int m0 = blockIdx.y * 128;
    int n0 = blockIdx.x * 128;
    const float* Ab = A + (size_t)m0 * DM;
    const float* Wb = W + (size_t)n0 * DM;

    auto issue = [&](int kt, int st) {
        float* sA = As + st * 128 * SAP;
        float* sW = Ws + st * 128 * SAP;
        int k0 = kt * 32;
        #pragma unroll
        for (int i = 0; i < 4; i++) {
            int c = tid + i * 256;          // 0..1023
            int row = c >> 3;
            int col = (c & 7) << 2;
            cpa16(sA + row * SAP + col, Ab + (size_t)row * DM + k0 + col);
            cpa16(sW + row * SAP + col, Wb + (size_t)row * DM + k0 + col);
        }
        CP_COMMIT();
    };

    issue(0, 0);
    issue(1, 1);

    int w    = tid >> 5;
    int lane = tid & 31;
    int wm = (w >> 1) * 32;
    int wn = (w & 1) * 64;
    int g = lane >> 2;
    int t = lane & 3;

    float acc[2][8][4] = {};

    const int NT = DM / 32;   // 32
    int st = 0, si = 2;
    for (int kt = 0; kt < NT; kt++) {
        if (kt + 2 < NT) {
            issue(kt + 2, si);
            si = (si == 2) ? 0 : si + 1;
            CP_WAIT(2);                 // pending <=2 (kt+1, kt+2) -> stage kt done
        } else if (kt + 1 < NT) {
            CP_WAIT(1);
        } else {
            CP_WAIT(0);
        }
        __syncthreads();

        const float* ab = As + st * 128 * SAP;
        const float* wb = Ws + st * 128 * SAP;
        #pragma unroll
        for (int ks = 0; ks < 4; ks++) {
            unsigned af[2][4];
            #pragma unroll
            for (int mt = 0; mt < 2; mt++) {
                const float* bp = ab + (wm + mt * 16 + g) * SAP + ks * 8 + t;
                af[mt][0] = __float_as_uint(bp[0]);
                af[mt][1] = __float_as_uint(bp[8 * SAP]);
                af[mt][2] = __float_as_uint(bp[4]);
                af[mt][3] = __float_as_uint(bp[8 * SAP + 4]);
            }
            #pragma unroll
            for (int nt = 0; nt < 8; nt++) {
                const float* bp = wb + (wn + nt * 8 + g) * SAP + ks * 8 + t;
                unsigned b0 = __float_as_uint(bp[0]);
                unsigned b1 = __float_as_uint(bp[4]);
                mma_tf32(acc[0][nt], af[0], b0, b1);
                mma_tf32(acc[1][nt], af[1], b0, b1);
            }
        }
        __syncthreads();   // all warps done with stage st before it is refilled
        st = (st == 2) ? 0 : st + 1;
    }

    #pragma unroll
    for (int mt = 0; mt < 2; mt++) {
        #pragma unroll
        for (int nt = 0; nt < 8; nt++) {
            int m = m0 + wm + mt * 16 + g;
            int n = n0 + wn + nt * 8 + t * 2;
            float bn0 = bias[n];
            float bn1 = bias[n + 1];
            float r0 = acc[mt][nt][0] + bn0;
            float r1 = acc[mt][nt][1] + bn1;
            float r2 = acc[mt][nt][2] + bn0;
            float r3 = acc[mt][nt][3] + bn1;
            if (round_out) {
                r0 = f2tf32(r0); r1 = f2tf32(r1); r2 = f2tf32(r2); r3 = f2tf32(r3);
            }
            *(float2*)&C[(size_t)m * DM + n]       = make_float2(r0, r1);
            *(float2*)&C[(size_t)(m + 8) * DM + n] = make_float2(r2, r3);
        }
    }
}

// =====================================================================
// Tensor-core flash attention, 2-stage cp.async KV pipeline,
// register quad-shuffle P transpose (no P smem roundtrip).
// CTA: 128 q-rows x one (b,h); 8 warps x 16 q-rows. KV tiles of 64.
// Inputs pre-rounded tf32; ctx written tf32-rounded.
// =====================================================================
#define QP2 68
#define VP2 72
#define FA_SMEM ((128 * QP2 + 2 * 64 * QP2 + 2 * 64 * VP2) * 4)   // 106496 B

__global__ void __launch_bounds__(256, 2) flash_mma(
    const float* __restrict__ Qg,
    const float* __restrict__ Kg,
    const float* __restrict__ Vg,
    float* __restrict__ Ctx)
{
    extern __shared__ float sm[];
    float* Qs = sm;                        // [128][QP2]
    float* Kd = Qs + 128 * QP2;            // [2][64][QP2]
    float* Vd = Kd + 2 * 64 * QP2;         // [2][64][VP2]

    int tid  = threadIdx.x;
    int w    = tid >> 5;
    int lane = tid & 31;
    int g = lane >> 2;
    int t = lane & 3;
    int wr = w * 16;

    int q0 = blockIdx.x * 128;
    int h  = blockIdx.y;
    int b  = blockIdx.z;

    const size_t base = (size_t)b * SQ * DM + (size_t)h * DK;
    const float* Qb = Qg + base;
    const float* Kb = Kg + base;
    const float* Vb = Vg + base;

    auto issue = [&](int it, int buf) {
        const float* ksrc = Kb + (size_t)(it * 64) * DM;
        const float* vsrc = Vb + (size_t)(it * 64) * DM;
        float* kdst = Kd + buf * 64 * QP2;
        float* vdst = Vd + buf * 64 * VP2;
        #pragma unroll
        for (int i = 0; i < 4; i++) {
            int c = tid + i * 256;         // 0..1023
            int row = c >> 4;
            int col = (c & 15) << 2;
            cpa16(kdst + row * QP2 + col, ksrc + (size_t)row * DM + col);
            cpa16(vdst + row * VP2 + col, vsrc + (size_t)row * DM + col);
        }
        CP_COMMIT();
    };

    issue(0, 0);

    // Q tile (already tf32-rounded): plain copy
    for (int i = tid; i < 128 * 16; i += 256) {
        int r  = i >> 4;
        int c4 = (i & 15) << 2;
        *(float4*)(Qs + r * QP2 + c4) = *(const float4*)(Qb + (size_t)(q0 + r) * DM + c4);
    }

    float m0 = -1e30f, m1 = -1e30f;
    float l0 = 0.0f,   l1 = 0.0f;
    float o[8][4] = {};
    const float CS = 0.125f * 1.44269504f;   // scale * log2(e)

    const int NT = SQ / 64;   // 32
    int src0 = (lane & ~3) | (t >> 1);
    bool odd = t & 1;

    for (int it = 0; it < NT; it++) {
        int buf = it & 1;
        if (it + 1 < NT) { issue(it + 1, buf ^ 1); CP_WAIT(1); }
        else             { CP_WAIT(0); }
        __syncthreads();

        const float* Ks = Kd + buf * 64 * QP2;
        const float* Vs = Vd + buf * 64 * VP2;

        // ---- S = Q @ K^T ----
        float sc[8][4] = {};
        #pragma unroll
        for (int ks = 0; ks < 8; ks++) {
            unsigned a[4];
            const float* ab = Qs + (wr + g) * QP2 + ks * 8 + t;
            a[0] = __float_as_uint(ab[0]);
            a[1] = __float_as_uint(ab[8 * QP2]);
            a[2] = __float_as_uint(ab[4]);
            a[3] = __float_as_uint(ab[8 * QP2 + 4]);
            #pragma unroll
            for (int nb = 0; nb < 8; nb++) {
                const float* bb = Ks + (nb * 8 + g) * QP2 + ks * 8 + t;
                mma_tf32(sc[nb], a, __float_as_uint(bb[0]), __float_as_uint(bb[4]));
            }
        }

        // ---- online softmax (log2 domain) ----
        float mx0 = m0, mx1 = m1;
        #pragma unroll
        for (int nb = 0; nb < 8; nb++) {
            sc[nb][0] *= CS; sc[nb][1] *= CS; sc[nb][2] *= CS; sc[nb][3] *= CS;
            mx0 = fmaxf(mx0, fmaxf(sc[nb][0], sc[nb][1]));
            mx1 = fmaxf(mx1, fmaxf(sc[nb][2], sc[nb][3]));
        }
        mx0 = fmaxf(mx0, __shfl_xor_sync(0xffffffffu, mx0, 1));
        mx0 = fmaxf(mx0, __shfl_xor_sync(0xffffffffu, mx0, 2));
        mx1 = fmaxf(mx1, __shfl_xor_sync(0xffffffffu, mx1, 1));
        mx1 = fmaxf(mx1, __shfl_xor_sync(0xffffffffu, mx1, 2));

        float a0 = ex2(m0 - mx0);
        float a1 = ex2(m1 - mx1);
        m0 = mx0; m1 = mx1;

        float s0 = 0.0f, s1 = 0.0f;
        #pragma unroll
        for (int nb = 0; nb < 8; nb++) {
            float e00 = ex2(sc[nb][0] - mx0);
            float e01 = ex2(sc[nb][1] - mx0);
            float e10 = ex2(sc[nb][2] - mx1);
            float e11 = ex2(sc[nb][3] - mx1);
            s0 += e00 + e01;
            s1 += e10 + e11;
            sc[nb][0] = f2tf32(e00);
            sc[nb][1] = f2tf32(e01);
            sc[nb][2] = f2tf32(e10);
            sc[nb][3] = f2tf32(e11);
        }
        s0 += __shfl_xor_sync(0xffffffffu, s0, 1);
        s0 += __shfl_xor_sync(0xffffffffu, s0, 2);
        s1 += __shfl_xor_sync(0xffffffffu, s1, 1);
        s1 += __shfl_xor_sync(0xffffffffu, s1, 2);
        l0 = l0 * a0 + s0;
        l1 = l1 * a1 + s1;

        #pragma unroll
        for (int nb = 0; nb < 8; nb++) {
            o[nb][0] *= a0; o[nb][1] *= a0;
            o[nb][2] *= a1; o[nb][3] *= a1;
        }

        // ---- O += P @ V : quad-shuffle transpose of P (C-layout -> A-frag) ----
        #pragma unroll
        for (int ks = 0; ks < 8; ks++) {
            float v00 = __shfl_sync(0xffffffffu, sc[ks][0], src0);
            float v01 = __shfl_sync(0xffffffffu, sc[ks][1], src0);
            float v10 = __shfl_sync(0xffffffffu, sc[ks][2], src0);
            float v11 = __shfl_sync(0xffffffffu, sc[ks][3], src0);
            float w00 = __shfl_sync(0xffffffffu, sc[ks][0], src0 + 2);
            float w01 = __shfl_sync(0xffffffffu, sc[ks][1], src0 + 2);
            float w10 = __shfl_sync(0xffffffffu, sc[ks][2], src0 + 2);
            float w11 = __shfl_sync(0xffffffffu, sc[ks][3], src0 + 2);
            unsigned a[4];
            a[0] = __float_as_uint(odd ? v01 : v00);   // row g,   col t
            a[1] = __float_as_uint(odd ? v11 : v10);   // row g+8, col t
            a[2] = __float_as_uint(odd ? w01 : w00);   // row g,   col t+4
            a[3] = __float_as_uint(odd ? w11 : w10);   // row g+8, col t+4
            #pragma unroll
            for (int nb = 0; nb < 8; nb++) {
                const float* vb = Vs + (ks * 8 + t) * VP2 + nb * 8 + g;
                mma_tf32(o[nb], a, __float_as_uint(vb[0]), __float_as_uint(vb[4 * VP2]));
            }
        }
        __syncthreads();   // all reads of this KV buffer done before refill
    }

    // ---- epilogue: normalize, round to tf32, write combined [B,S,H*dk] ----
    float il0 = 1.0f / l0;
    float il1 = 1.0f / l1;
    float* out0 = Ctx + (size_t)b * SQ * DM + (size_t)(q0 + wr + g) * DM + h * DK;
    float* out1 = out0 + 8 * DM;
    #pragma unroll
    for (int nb = 0; nb < 8; nb++) {
        *(float2*)(out0 + nb * 8 + 2 * t) =
            make_float2(f2tf32(o[nb][0] * il0), f2tf32(o[nb][1] * il0));
        *(float2*)(out1 + nb * 8 + 2 * t) =
            make_float2(f2tf32(o[nb][2] * il1), f2tf32(o[nb][3] * il1));
    }
}

// ---------------- launch ----------------
extern "C" void kernel_launch(void* const* d_in, const int* in_sizes, int n_in,
                              void* d_out, int out_size)
{
    const float* q   = (const float*)d_in[0];
    const float* k   = (const float*)d_in[1];
    const float* v   = (const float*)d_in[2];
    const float* W_q = (const float*)d_in[3];
    const float* b_q = (const float*)d_in[4];
    const float* W_k = (const float*)d_in[5];
    const float* b_k = (const float*)d_in[6];
    const float* W_v = (const float*)d_in[7];
    const float* b_v = (const float*)d_in[8];
    const float* W_o = (const float*)d_in[9];
    const float* b_o = (const float*)d_in[10];
    float* out = (float*)d_out;

    float *gq, *gk, *gv, *gctx, *grq, *grk, *grv, *gwq, *gwk, *gwv, *gwo;
    cudaGetSymbolAddress((void**)&gq,  g_q);
    cudaGetSymbolAddress((void**)&gk,  g_k);
    cudaGetSymbolAddress((void**)&gv,  g_v);
    cudaGetSymbolAddress((void**)&gctx, g_ctx);
    cudaGetSymbolAddress((void**)&grq, g_rq);
    cudaGetSymbolAddress((void**)&grk, g_rk);
    cudaGetSymbolAddress((void**)&grv, g_rv);
    cudaGetSymbolAddress((void**)&gwq, g_wq);
    cudaGetSymbolAddress((void**)&gwk, g_wk);
    cudaGetSymbolAddress((void**)&gwv, g_wv);
    cudaGetSymbolAddress((void**)&gwo, g_wo);

    // prepass: round activations + weights to tf32 (2 fused launches)
    const int NA4 = MROWS * DM / 4;   // 1048576
    const int NW4 = DM * DM / 4;      // 262144
    round_act<<<dim3(NA4 / 256, 3), 256>>>(
        (const float4*)q, (const float4*)k, (const float4*)v,
        (float4*)grq, (float4*)grk, (float4*)grv, NA4);
    round_w<<<dim3(NW4 / 256, 4), 256>>>(
        (const float4*)W_q, (const float4*)W_k, (const float4*)W_v, (const float4*)W_o,
        (float4*)gwq, (float4*)gwk, (float4*)gwv, (float4*)gwo, NW4);

    cudaFuncSetAttribute(gemm3, cudaFuncAttributeMaxDynamicSharedMemorySize, GEMM_SMEM);
    cudaFuncSetAttribute(flash_mma, cudaFuncAttributeMaxDynamicSharedMemorySize, FA_SMEM);

    // fused Q/K/V projections (rounded tf32 outputs)   [call-index 2]
    gemm3<<<dim3(DM / 128, MROWS / 128, 3), 256, GEMM_SMEM>>>(
        grq, grk, grv, gwq, gwk, gwv, b_q, b_k, b_v, gq, gk, gv, 1);

    // flash attention  [call-index 3 -> global ncu skip-5 slot]
    flash_mma<<<dim3(SQ / 128, NH, BQ), 256, FA_SMEM>>>(gq, gk, gv, gctx);

    // output projection (fp32 output)
    gemm3<<<dim3(DM / 128, MROWS / 128, 1), 256, GEMM_SMEM>>>(
        gctx, gctx, gctx, gwo, gwo, gwo, b_o, b_o, b_o, out, out, out, 0);
}

// round 14
// speedup vs baseline: 1.5985x; 1.0759x over previous
#include <cuda_runtime.h>
#include <cuda_bf16.h>
#include <math.h>

// Problem constants
#define BQ 2
#define SQ 2048
#define DM 1024
#define NH 16
#define DK 64
#define MROWS (BQ*SQ)   // 4096

// ---------------- scratch (allocation-free rule: __device__ globals) ----------------
__device__ float g_q[MROWS * DM];
__device__ float g_k[MROWS * DM];
__device__ float g_v[MROWS * DM];
__device__ float g_ctx[MROWS * DM];
__device__ float g_rq[MROWS * DM];
__device__ float g_rk[MROWS * DM];
__device__ float g_rv[MROWS * DM];
__device__ float g_wq[DM * DM];
__device__ float g_wk[DM * DM];
__device__ float g_wv[DM * DM];
__device__ float g_wo[DM * DM];

// =====================================================================
// helpers
// =====================================================================
__device__ __forceinline__ float f2tf32(float f) {
    unsigned r;
    asm("cvt.rna.tf32.f32 %0, %1;" : "=r"(r) : "f"(f));
    return __uint_as_float(r);
}

__device__ __forceinline__ void mma_tf32(float* c, const unsigned* a, unsigned b0, unsigned b1) {
    asm volatile(
        "mma.sync.aligned.m16n8k8.row.col.f32.tf32.tf32.f32 "
        "{%0,%1,%2,%3}, {%4,%5,%6,%7}, {%8,%9}, {%0,%1,%2,%3};"
        : "+f"(c[0]), "+f"(c[1]), "+f"(c[2]), "+f"(c[3])
        : "r"(a[0]), "r"(a[1]), "r"(a[2]), "r"(a[3]), "r"(b0), "r"(b1));
}

__device__ __forceinline__ float ex2(float x) {
    float y;
    asm("ex2.approx.f32 %0, %1;" : "=f"(y) : "f"(x));
    return y;
}

__device__ __forceinline__ void cpa16(float* s, const float* g) {
    unsigned a = (unsigned)__cvta_generic_to_shared(s);
    asm volatile("cp.async.ca.shared.global [%0], [%1], 16;" :: "r"(a), "l"(g));
}
#define CP_COMMIT() asm volatile("cp.async.commit_group;")
#define CP_WAIT(n)  asm volatile("cp.async.wait_group %0;" :: "n"(n))

// =====================================================================
// prepass: round tensors to tf32 (RNA) into scratch.
// =====================================================================
__global__ void __launch_bounds__(256) round_act(
    const float4* __restrict__ i0, const float4* __restrict__ i1, const float4* __restrict__ i2,
    float4* __restrict__ o0, float4* __restrict__ o1, float4* __restrict__ o2, int n4)
{
    int z = blockIdx.y;
    const float4* in = (z == 0) ? i0 : (z == 1) ? i1 : i2;
    float4* out      = (z == 0) ? o0 : (z == 1) ? o1 : o2;
    int i = blockIdx.x * 256 + threadIdx.x;
    if (i < n4) {
        float4 v = in[i];
        out[i] = make_float4(f2tf32(v.x), f2tf32(v.y), f2tf32(v.z), f2tf32(v.w));
    }
}

__global__ void __launch_bounds__(256) round_w(
    const float4* __restrict__ i0, const float4* __restrict__ i1,
    const float4* __restrict__ i2, const float4* __restrict__ i3,
    float4* __restrict__ o0, float4* __restrict__ o1,
    float4* __restrict__ o2, float4* __restrict__ o3, int n4)
{
    int z = blockIdx.y;
    const float4* in = (z == 0) ? i0 : (z == 1) ? i1 : (z == 2) ? i2 : i3;
    float4* out      = (z == 0) ? o0 : (z == 1) ? o1 : (z == 2) ? o2 : o3;
    int i = blockIdx.x * 256 + threadIdx.x;
    if (i < n4) {
        float4 v = in[i];
        out[i] = make_float4(f2tf32(v.x), f2tf32(v.y), f2tf32(v.z), f2tf32(v.w));
    }
}

// =====================================================================
// Pipelined tf32 GEMM (unchanged from R6/R11 known-good)
// =====================================================================
#define SAP 36
#define GSTG 3
#define GEMM_SMEM (2 * GSTG * 128 * SAP * 4)   // 110592 B

__global__ void __launch_bounds__(256, 2) gemm3(
    const float* __restrict__ A0, const float* __restrict__ A1, const float* __restrict__ A2,
    const float* __restrict__ W0, const float* __restrict__ W1, const float* __restrict__ W2,
    const float* __restrict__ B0, const float* __restrict__ B1, const float* __restrict__ B2,
    float* __restrict__ C0, float* __restrict__ C1, float* __restrict__ C2,
    int round_out)
{
    extern __shared__ float sm[];
    float* As = sm;                         // [3][128*SAP]
    float* Ws = sm + GSTG * 128 * SAP;      // [3][128*SAP]

    int z = blockIdx.z;
    const float* A    = (z == 0) ? A0 : (z == 1) ? A1 : A2;
    const float* W    = (z == 0) ? W0 : (z == 1) ? W1 : W2;
    const float* bias = (z == 0) ? B0 : (z == 1) ? B1 : B2;
    float*       C    = (z == 0) ? C0 : (z == 1) ? C1 : C2;

    int tid = threadIdx.x;
    int m0 = blockIdx.y * 128;
    int n0 = blockIdx.x * 128;
    const float* Ab = A + (size_t)m0 * DM;
    const float* Wb = W + (size_t)n0 * DM;

    auto issue = [&](int kt, int st) {
        float* sA = As + st * 128 * SAP;
        float* sW = Ws + st * 128 * SAP;
        int k0 = kt * 32;
        #pragma unroll
        for (int i = 0; i < 4; i++) {
            int c = tid + i * 256;
            int row = c >> 3;
            int col = (c & 7) << 2;
            cpa16(sA + row * SAP + col, Ab + (size_t)row * DM + k0 + col);
            cpa16(sW + row * SAP + col, Wb + (size_t)row * DM + k0 + col);
        }
        CP_COMMIT();
    };

    issue(0, 0);
    issue(1, 1);

    int w    = tid >> 5;
    int lane = tid & 31;
    int wm = (w >> 1) * 32;
    int wn = (w & 1) * 64;
    int g = lane >> 2;
    int t = lane & 3;

    float acc[2][8][4] = {};

    const int NT = DM / 32;   // 32
    int st = 0, si = 2;
    for (int kt = 0; kt < NT; kt++) {
        if (kt + 2 < NT) {
            issue(kt + 2, si);
            si = (si == 2) ? 0 : si + 1;
            CP_WAIT(2);
        } else if (kt + 1 < NT) {
            CP_WAIT(1);
        } else {
            CP_WAIT(0);
        }
        __syncthreads();

        const float* ab = As + st * 128 * SAP;
        const float* wb = Ws + st * 128 * SAP;
        #pragma unroll
        for (int ks = 0; ks < 4; ks++) {
            unsigned af[2][4];
            #pragma unroll
            for (int mt = 0; mt < 2; mt++) {
                const float* bp = ab + (wm + mt * 16 + g) * SAP + ks * 8 + t;
                af[mt][0] = __float_as_uint(bp[0]);
                af[mt][1] = __float_as_uint(bp[8 * SAP]);
                af[mt][2] = __float_as_uint(bp[4]);
                af[mt][3] = __float_as_uint(bp[8 * SAP + 4]);
            }
            #pragma unroll
            for (int nt = 0; nt < 8; nt++) {
                const float* bp = wb + (wn + nt * 8 + g) * SAP + ks * 8 + t;
                unsigned b0 = __float_as_uint(bp[0]);
                unsigned b1 = __float_as_uint(bp[4]);
                mma_tf32(acc[0][nt], af[0], b0, b1);
                mma_tf32(acc[1][nt], af[1], b0, b1);
            }
        }
        __syncthreads();
        st = (st == 2) ? 0 : st + 1;
    }

    #pragma unroll
    for (int mt = 0; mt < 2; mt++) {
        #pragma unroll
        for (int nt = 0; nt < 8; nt++) {
            int m = m0 + wm + mt * 16 + g;
            int n = n0 + wn + nt * 8 + t * 2;
            float bn0 = bias[n];
            float bn1 = bias[n + 1];
            float r0 = acc[mt][nt][0] + bn0;
            float r1 = acc[mt][nt][1] + bn1;
            float r2 = acc[mt][nt][2] + bn0;
            float r3 = acc[mt][nt][3] + bn1;
            if (round_out) {
                r0 = f2tf32(r0); r1 = f2tf32(r1); r2 = f2tf32(r2); r3 = f2tf32(r3);
            }
            *(float2*)&C[(size_t)m * DM + n]       = make_float2(r0, r1);
            *(float2*)&C[(size_t)(m + 8) * DM + n] = make_float2(r2, r3);
        }
    }
}

// =====================================================================
// Tensor-core flash attention, m32 warp tiles (K/V fragment reuse x2),
// 2-stage cp.async KV pipeline, quad-shuffle P transpose.
// CTA: 256 q-rows x one (b,h); 8 warps, each owns 32 q-rows (2 x m16).
// KV tiles of 64. 1 CTA/SM (141KB smem).
// =====================================================================
#define QROWS 256
#define QP2 68
#define VP2 72
#define FA_SMEM ((QROWS * QP2 + 2 * 64 * QP2 + 2 * 64 * VP2) * 4)   // 141312 B

__global__ void __launch_bounds__(256, 1) flash_mma(
    const float* __restrict__ Qg,
    const float* __restrict__ Kg,
    const float* __restrict__ Vg,
    float* __restrict__ Ctx)
{
    extern __shared__ float sm[];
    float* Qs = sm;                           // [256][QP2]
    float* Kd = Qs + QROWS * QP2;             // [2][64][QP2]
    float* Vd = Kd + 2 * 64 * QP2;            // [2][64][VP2]

    int tid  = threadIdx.x;
    int w    = tid >> 5;
    int lane = tid & 31;
    int g = lane >> 2;
    int t = lane & 3;
    int wr = w * 32;          // warp q-row base (2 x m16 tiles)

    int q0 = blockIdx.x * QROWS;
    int h  = blockIdx.y;
    int b  = blockIdx.z;

    const size_t base = (size_t)b * SQ * DM + (size_t)h * DK;
    const float* Qb = Qg + base;
    const float* Kb = Kg + base;
    const float* Vb = Vg + base;

    auto issue = [&](int it, int buf) {
        const float* ksrc = Kb + (size_t)(it * 64) * DM;
        const float* vsrc = Vb + (size_t)(it * 64) * DM;
        float* kdst = Kd + buf * 64 * QP2;
        float* vdst = Vd + buf * 64 * VP2;
        #pragma unroll
        for (int i = 0; i < 4; i++) {
            int c = tid + i * 256;         // 0..1023
            int row = c >> 4;
            int col = (c & 15) << 2;
            cpa16(kdst + row * QP2 + col, ksrc + (size_t)row * DM + col);
            cpa16(vdst + row * VP2 + col, vsrc + (size_t)row * DM + col);
        }
        CP_COMMIT();
    };

    issue(0, 0);

    // Q tile (already tf32-rounded): plain copy, 256 rows
    for (int i = tid; i < QROWS * 16; i += 256) {
        int r  = i >> 4;
        int c4 = (i & 15) << 2;
        *(float4*)(Qs + r * QP2 + c4) = *(const float4*)(Qb + (size_t)(q0 + r) * DM + c4);
    }

    // softmax state per m-tile (rows g / g+8 of each 16-row tile)
    float mr[2][2] = {{-1e30f, -1e30f}, {-1e30f, -1e30f}};
    float lr[2][2] = {{0.0f, 0.0f}, {0.0f, 0.0f}};
    float o[2][8][4] = {};
    const float CS = 0.125f * 1.44269504f;   // scale * log2(e)

    const int NT = SQ / 64;   // 32
    int src0 = (lane & ~3) | (t >> 1);
    bool odd = t & 1;

    for (int it = 0; it < NT; it++) {
        int buf = it & 1;
        if (it + 1 < NT) { issue(it + 1, buf ^ 1); CP_WAIT(1); }
        else             { CP_WAIT(0); }
        __syncthreads();

        const float* Ks = Kd + buf * 64 * QP2;
        const float* Vs = Vd + buf * 64 * VP2;

        // ---- S = Q @ K^T for both m-tiles; K fragments loaded once ----
        float sc[2][8][4] = {};
        #pragma unroll
        for (int ks = 0; ks < 8; ks++) {
            unsigned a[2][4];
            #pragma unroll
            for (int mt = 0; mt < 2; mt++) {
                const float* ab = Qs + (wr + mt * 16 + g) * QP2 + ks * 8 + t;
                a[mt][0] = __float_as_uint(ab[0]);
                a[mt][1] = __float_as_uint(ab[8 * QP2]);
                a[mt][2] = __float_as_uint(ab[4]);
                a[mt][3] = __float_as_uint(ab[8 * QP2 + 4]);
            }
            #pragma unroll
            for (int nb = 0; nb < 8; nb++) {
                const float* bb = Ks + (nb * 8 + g) * QP2 + ks * 8 + t;
                unsigned b0 = __float_as_uint(bb[0]);
                unsigned b1 = __float_as_uint(bb[4]);
                mma_tf32(sc[0][nb], a[0], b0, b1);
                mma_tf32(sc[1][nb], a[1], b0, b1);
            }
        }

        // ---- online softmax (log2 domain), per m-tile ----
        float aa[2][2];
        #pragma unroll
        for (int mt = 0; mt < 2; mt++) {
            float mx0 = mr[mt][0], mx1 = mr[mt][1];
            #pragma unroll
            for (int nb = 0; nb < 8; nb++) {
                sc[mt][nb][0] *= CS; sc[mt][nb][1] *= CS;
                sc[mt][nb][2] *= CS; sc[mt][nb][3] *= CS;
                mx0 = fmaxf(mx0, fmaxf(sc[mt][nb][0], sc[mt][nb][1]));
                mx1 = fmaxf(mx1, fmaxf(sc[mt][nb][2], sc[mt][nb][3]));
            }
            mx0 = fmaxf(mx0, __shfl_xor_sync(0xffffffffu, mx0, 1));
            mx0 = fmaxf(mx0, __shfl_xor_sync(0xffffffffu, mx0, 2));
            mx1 = fmaxf(mx1, __shfl_xor_sync(0xffffffffu, mx1, 1));
            mx1 = fmaxf(mx1, __shfl_xor_sync(0xffffffffu, mx1, 2));

            float a0 = ex2(mr[mt][0] - mx0);
            float a1 = ex2(mr[mt][1] - mx1);
            mr[mt][0] = mx0; mr[mt][1] = mx1;

            float s0 = 0.0f, s1 = 0.0f;
            #pragma unroll
            for (int nb = 0; nb < 8; nb++) {
                float e00 = ex2(sc[mt][nb][0] - mx0);
                float e01 = ex2(sc[mt][nb][1] - mx0);
                float e10 = ex2(sc[mt][nb][2] - mx1);
                float e11 = ex2(sc[mt][nb][3] - mx1);
                s0 += e00 + e01;
                s1 += e10 + e11;
                sc[mt][nb][0] = f2tf32(e00);
                sc[mt][nb][1] = f2tf32(e01);
                sc[mt][nb][2] = f2tf32(e10);
                sc[mt][nb][3] = f2tf32(e11);
            }
            s0 += __shfl_xor_sync(0xffffffffu, s0, 1);
            s0 += __shfl_xor_sync(0xffffffffu, s0, 2);
            s1 += __shfl_xor_sync(0xffffffffu, s1, 1);
            s1 += __shfl_xor_sync(0xffffffffu, s1, 2);
            lr[mt][0] = lr[mt][0] * a0 + s0;
            lr[mt][1] = lr[mt][1] * a1 + s1;

            #pragma unroll
            for (int nb = 0; nb < 8; nb++) {
                o[mt][nb][0] *= a0; o[mt][nb][1] *= a0;
                o[mt][nb][2] *= a1; o[mt][nb][3] *= a1;
            }
            aa[mt][0] = a0; aa[mt][1] = a1;
        }
        (void)aa;

        // ---- O += P @ V : quad-shuffle transpose; V fragments loaded once ----
        #pragma unroll
        for (int ks = 0; ks < 8; ks++) {
            unsigned a[2][4];
            #pragma unroll
            for (int mt = 0; mt < 2; mt++) {
                float v00 = __shfl_sync(0xffffffffu, sc[mt][ks][0], src0);
                float v01 = __shfl_sync(0xffffffffu, sc[mt][ks][1], src0);
                float v10 = __shfl_sync(0xffffffffu, sc[mt][ks][2], src0);
                float v11 = __shfl_sync(0xffffffffu, sc[mt][ks][3], src0);
                float w00 = __shfl_sync(0xffffffffu, sc[mt][ks][0], src0 + 2);
                float w01 = __shfl_sync(0xffffffffu, sc[mt][ks][1], src0 + 2);
                float w10 = __shfl_sync(0xffffffffu, sc[mt][ks][2], src0 + 2);
                float w11 = __shfl_sync(0xffffffffu, sc[mt][ks][3], src0 + 2);
                a[mt][0] = __float_as_uint(odd ? v01 : v00);
                a[mt][1] = __float_as_uint(odd ? v11 : v10);
                a[mt][2] = __float_as_uint(odd ? w01 : w00);
                a[mt][3] = __float_as_uint(odd ? w11 : w10);
            }
            #pragma unroll
            for (int nb = 0; nb < 8; nb++) {
                const float* vb = Vs + (ks * 8 + t) * VP2 + nb * 8 + g;
                unsigned b0 = __float_as_uint(vb[0]);
                unsigned b1 = __float_as_uint(vb[4 * VP2]);
                mma_tf32(o[0][nb], a[0], b0, b1);
                mma_tf32(o[1][nb], a[1], b0, b1);
            }
        }
        __syncthreads();   // all reads of this KV buffer done before refill
    }

    // ---- epilogue: normalize, round to tf32, write combined [B,S,H*dk] ----
    #pragma unroll
    for (int mt = 0; mt < 2; mt++) {
        float il0 = 1.0f / lr[mt][0];
        float il1 = 1.0f / lr[mt][1];
        float* out0 = Ctx + (size_t)b * SQ * DM
                    + (size_t)(q0 + wr + mt * 16 + g) * DM + h * DK;
        float* out1 = out0 + 8 * DM;
        #pragma unroll
        for (int nb = 0; nb < 8; nb++) {
            *(float2*)(out0 + nb * 8 + 2 * t) =
                make_float2(f2tf32(o[mt][nb][0] * il0), f2tf32(o[mt][nb][1] * il0));
            *(float2*)(out1 + nb * 8 + 2 * t) =
                make_float2(f2tf32(o[mt][nb][2] * il1), f2tf32(o[mt][nb][3] * il1));
        }
    }
}

// ---------------- launch ----------------
extern "C" void kernel_launch(void* const* d_in, const int* in_sizes, int n_in,
                              void* d_out, int out_size)
{
    const float* q   = (const float*)d_in[0];
    const float* k   = (const float*)d_in[1];
    const float* v   = (const float*)d_in[2];
    const float* W_q = (const float*)d_in[3];
    const float* b_q = (const float*)d_in[4];
    const float* W_k = (const float*)d_in[5];
    const float* b_k = (const float*)d_in[6];
    const float* W_v = (const float*)d_in[7];
    const float* b_v = (const float*)d_in[8];
    const float* W_o = (const float*)d_in[9];
    const float* b_o = (const float*)d_in[10];
    float* out = (float*)d_out;

    float *gq, *gk, *gv, *gctx, *grq, *grk, *grv, *gwq, *gwk, *gwv, *gwo;
    cudaGetSymbolAddress((void**)&gq,  g_q);
    cudaGetSymbolAddress((void**)&gk,  g_k);
    cudaGetSymbolAddress((void**)&gv,  g_v);
    cudaGetSymbolAddress((void**)&gctx, g_ctx);
    cudaGetSymbolAddress((void**)&grq, g_rq);
    cudaGetSymbolAddress((void**)&grk, g_rk);
    cudaGetSymbolAddress((void**)&grv, g_rv);
    cudaGetSymbolAddress((void**)&gwq, g_wq);
    cudaGetSymbolAddress((void**)&gwk, g_wk);
    cudaGetSymbolAddress((void**)&gwv, g_wv);
    cudaGetSymbolAddress((void**)&gwo, g_wo);

    // prepass: round activations + weights to tf32 (2 fused launches)
    const int NA4 = MROWS * DM / 4;   // 1048576
    const int NW4 = DM * DM / 4;      // 262144
    round_act<<<dim3(NA4 / 256, 3), 256>>>(
        (const float4*)q, (const float4*)k, (const float4*)v,
        (float4*)grq, (float4*)grk, (float4*)grv, NA4);
    round_w<<<dim3(NW4 / 256, 4), 256>>>(
        (const float4*)W_q, (const float4*)W_k, (const float4*)W_v, (const float4*)W_o,
        (float4*)gwq, (float4*)gwk, (float4*)gwv, (float4*)gwo, NW4);

    cudaFuncSetAttribute(gemm3, cudaFuncAttributeMaxDynamicSharedMemorySize, GEMM_SMEM);
    cudaFuncSetAttribute(flash_mma, cudaFuncAttributeMaxDynamicSharedMemorySize, FA_SMEM);

    // fused Q/K/V projections (rounded tf32 outputs)   [call-index 2]
    gemm3<<<dim3(DM / 128, MROWS / 128, 3), 256, GEMM_SMEM>>>(
        grq, grk, grv, gwq, gwk, gwv, b_q, b_k, b_v, gq, gk, gv, 1);

    // flash attention  [call-index 3 -> global ncu skip-5 slot]
    flash_mma<<<dim3(SQ / QROWS, NH, BQ), 256, FA_SMEM>>>(gq, gk, gv, gctx);

    // output projection (fp32 output)
    gemm3<<<dim3(DM / 128, MROWS / 128, 1), 256, GEMM_SMEM>>>(
        gctx, gctx, gctx, gwo, gwo, gwo, b_o, b_o, b_o, out, out, out, 0);
}